// round 15
// baseline (speedup 1.0000x reference)
#include <cuda_runtime.h>
#include <cstdint>

// Problem dimensions (fixed by the reference)
#define BB 64
#define TT 512
#define DD 1024
#define UU 128

// Scratch for logits [B, T, U] fp32 = 16 MB (device global: no allocs allowed)
__device__ float g_logits[BB * TT * UU];

// ---------------------------------------------------------------------------
// Packed f32x2 helpers (full-rate FMA pipe on sm_103a; FFMA 3-reg is half-rate)
// ---------------------------------------------------------------------------
__device__ __forceinline__ unsigned long long pack2same(float a) {
    unsigned long long r;
    asm("mov.b64 %0, {%1, %1};" : "=l"(r) : "r"(__float_as_uint(a)));
    return r;
}
__device__ __forceinline__ void fma2(unsigned long long& d,
                                     unsigned long long a,
                                     unsigned long long b) {
    asm("fma.rn.f32x2 %0, %1, %2, %0;" : "+l"(d) : "l"(a), "l"(b));
}
__device__ __forceinline__ void unpack2(unsigned long long v, float& lo, float& hi) {
    unsigned int a, b;
    asm("mov.b64 {%0, %1}, %2;" : "=r"(a), "=r"(b) : "l"(v));
    lo = __uint_as_float(a);
    hi = __uint_as_float(b);
}

// ---------------------------------------------------------------------------
// GEMM: logits[m, u] = sum_d X[m, d] * W[d, u] + bias[u]
// M = B*T = 32768, N = 128, K = 1024. Tile 128x128, TK=16, 256 threads,
// each thread an 8x8 micro-tile held as 8x4 f32x2 accumulators.
// ---------------------------------------------------------------------------
#define TMr 128
#define TNr 128
#define TKr 16

__global__ __launch_bounds__(256)
void crf_gemm_kernel(const float* __restrict__ X,
                     const float* __restrict__ W,
                     const float* __restrict__ bias) {
    __shared__ float As[TKr * TMr];  // transposed: As[k][m]
    __shared__ float Bs[TKr * TNr];  // Bs[k][n]

    const int tid = threadIdx.x;
    const int tx = tid & 15;   // 16 col-groups of 8
    const int ty = tid >> 4;   // 16 row-groups of 8
    const long row0 = (long)blockIdx.x * TMr;

    unsigned long long acc[8][4];
#pragma unroll
    for (int r = 0; r < 8; ++r)
#pragma unroll
        for (int p = 0; p < 4; ++p) acc[r][p] = 0ULL;

    for (int kb = 0; kb < DD; kb += TKr) {
        // Load A tile (128 rows x 16 k) transposed into As[k][m]
#pragma unroll
        for (int q = 0; q < 2; ++q) {
            int idx4 = tid * 2 + q;          // 0..511 float4s
            int m = idx4 >> 2;               // 4 float4 per row (TK=16)
            int kq = (idx4 & 3) * 4;
            float4 f = *(const float4*)&X[(row0 + m) * DD + kb + kq];
            As[(kq + 0) * TMr + m] = f.x;
            As[(kq + 1) * TMr + m] = f.y;
            As[(kq + 2) * TMr + m] = f.z;
            As[(kq + 3) * TMr + m] = f.w;
        }
        // Load B tile (16 k x 128 n)
#pragma unroll
        for (int q = 0; q < 2; ++q) {
            int idx4 = tid * 2 + q;          // 0..511 float4s
            int k = idx4 >> 5;               // 32 float4 per row (TN=128)
            int n4 = (idx4 & 31) * 4;
            *(float4*)&Bs[k * TNr + n4] =
                *(const float4*)&W[(long)(kb + k) * UU + n4];
        }
        __syncthreads();

#pragma unroll
        for (int k = 0; k < TKr; ++k) {
            float4 a0 = *(const float4*)&As[k * TMr + ty * 8];
            float4 a1 = *(const float4*)&As[k * TMr + ty * 8 + 4];
            float av[8] = {a0.x, a0.y, a0.z, a0.w, a1.x, a1.y, a1.z, a1.w};
            ulonglong2 b01 = *(const ulonglong2*)&Bs[k * TNr + tx * 8];
            ulonglong2 b23 = *(const ulonglong2*)&Bs[k * TNr + tx * 8 + 4];
            unsigned long long bb[4] = {b01.x, b01.y, b23.x, b23.y};
#pragma unroll
            for (int r = 0; r < 8; ++r) {
                unsigned long long ap = pack2same(av[r]);
#pragma unroll
                for (int p = 0; p < 4; ++p) fma2(acc[r][p], ap, bb[p]);
            }
        }
        __syncthreads();
    }

    // Epilogue: + bias, store to g_logits
    float4 bv0 = *(const float4*)&bias[tx * 8];
    float4 bv1 = *(const float4*)&bias[tx * 8 + 4];
    float bcol[8] = {bv0.x, bv0.y, bv0.z, bv0.w, bv1.x, bv1.y, bv1.z, bv1.w};

#pragma unroll
    for (int r = 0; r < 8; ++r) {
        float o[8];
#pragma unroll
        for (int p = 0; p < 4; ++p) unpack2(acc[r][p], o[2 * p], o[2 * p + 1]);
#pragma unroll
        for (int c = 0; c < 8; ++c) o[c] += bcol[c];
        long row = row0 + ty * 8 + r;
        *(float4*)&g_logits[row * UU + tx * 8] =
            make_float4(o[0], o[1], o[2], o[3]);
        *(float4*)&g_logits[row * UU + tx * 8 + 4] =
            make_float4(o[4], o[5], o[6], o[7]);
    }
}

// ---------------------------------------------------------------------------
// Viterbi: one CTA per batch, 512 threads = 4 i-slices x 128 j.
// trans transposed in SMEM, stride 132 (conflict-free LDS.128).
// Backpointers kept in SMEM (511 x 128 uint8) so backtrace is LDS-latency.
// Tie-breaking matches jnp.argmax (first max) via strict-> updates and
// ascending slice merge order.
// ---------------------------------------------------------------------------
#define SM_TRANS_STRIDE 132
// smem layout sizes (bytes):
//   transT : 128*132*4 = 67584
//   v      : 128*4     = 512
//   redv   : 512*4     = 2048
//   redi   : 512*4     = 2048
//   bp     : 511*128   = 65408
#define VIT_SMEM_BYTES (67584 + 512 + 2048 + 2048 + 65408)

__global__ __launch_bounds__(512, 1)
void crf_viterbi_kernel(const float* __restrict__ trans,
                        const float* __restrict__ lb,
                        const float* __restrict__ rb,
                        float* __restrict__ out) {
    extern __shared__ char smem[];
    float* transT = (float*)smem;                       // [128][132]
    float* v = transT + UU * SM_TRANS_STRIDE;           // [128]
    float* redv = v + UU;                               // [512]
    int* redi = (int*)(redv + 512);                     // [512]
    unsigned char* bp = (unsigned char*)(redi + 512);   // [511][128]

    const int tid = threadIdx.x;
    const int b = blockIdx.x;
    const float* lg_base = g_logits + (size_t)b * TT * UU;

    // Load transposed transition matrix: transT[j][i] = trans[i][j]
    for (int idx = tid; idx < UU * UU; idx += 512) {
        int i = idx >> 7;
        int jj = idx & 127;
        transT[jj * SM_TRANS_STRIDE + i] = trans[idx];
    }
    // Init v with t=0 logits + left boundary
    if (tid < UU) v[tid] = lg_base[tid] + lb[tid];
    __syncthreads();

    const int j = tid & 127;
    const int s = tid >> 7;          // i-slice 0..3
    const int ibase = s * 32;
    const float4* trow = (const float4*)(transT + j * SM_TRANS_STRIDE + ibase);
    const float4* vrow = (const float4*)(v + ibase);

    for (int t = 1; t < TT; ++t) {
        // Prefetch this step's logit (consumed after the barrier)
        float lg = 0.0f;
        if (tid < UU) {
            lg = lg_base[t * UU + tid];
            if (t == TT - 1) lg += rb[tid];
        }

        // Partial max/argmax over this thread's 32 i's
        float m = -3.4e38f;
        int bi = ibase;
#pragma unroll
        for (int k = 0; k < 8; ++k) {
            float4 tr = trow[k];
            float4 vv = vrow[k];   // broadcast (same addr across warp)
            float s0 = vv.x + tr.x;
            float s1 = vv.y + tr.y;
            float s2 = vv.z + tr.z;
            float s3 = vv.w + tr.w;
            if (s0 > m) { m = s0; bi = ibase + 4 * k + 0; }
            if (s1 > m) { m = s1; bi = ibase + 4 * k + 1; }
            if (s2 > m) { m = s2; bi = ibase + 4 * k + 2; }
            if (s3 > m) { m = s3; bi = ibase + 4 * k + 3; }
        }
        redv[tid] = m;
        redi[tid] = bi;
        __syncthreads();

        if (tid < UU) {
            float best = redv[tid];
            int bidx = redi[tid];
#pragma unroll
            for (int ss = 1; ss < 4; ++ss) {
                float c = redv[ss * 128 + tid];
                int ci = redi[ss * 128 + tid];
                if (c > best) { best = c; bidx = ci; }  // strict: lowest i wins ties
            }
            v[tid] = best + lg;
            bp[(t - 1) * UU + tid] = (unsigned char)bidx;
        }
        __syncthreads();
    }

    // Final argmax (first max) + backtrace — SMEM pointer chase, ~29 cyc/step
    if (tid == 0) {
        float best = v[0];
        int tag = 0;
        for (int jj = 1; jj < UU; ++jj) {
            if (v[jj] > best) { best = v[jj]; tag = jj; }
        }
        out[(size_t)b * TT + (TT - 1)] = (float)tag;
        for (int t = TT - 2; t >= 0; --t) {
            tag = bp[t * UU + tag];
            out[(size_t)b * TT + t] = (float)tag;
        }
    }
}

// ---------------------------------------------------------------------------
extern "C" void kernel_launch(void* const* d_in, const int* in_sizes, int n_in,
                              void* d_out, int out_size) {
    const float* x = (const float*)d_in[0];       // [64, 512, 1024]
    const float* kernel = (const float*)d_in[1];  // [1024, 128]
    const float* bias = (const float*)d_in[2];    // [128]
    const float* trans = (const float*)d_in[3];   // [128, 128]
    const float* lb = (const float*)d_in[4];      // [128]
    const float* rb = (const float*)d_in[5];      // [128]
    float* out = (float*)d_out;                   // [64, 512] float32

    static bool attr_set = false;
    if (!attr_set) {
        cudaFuncSetAttribute(crf_viterbi_kernel,
                             cudaFuncAttributeMaxDynamicSharedMemorySize,
                             VIT_SMEM_BYTES);
        attr_set = true;
    }

    // GEMM: 32768 rows / 128 per block = 256 blocks
    crf_gemm_kernel<<<(BB * TT) / TMr, 256>>>(x, kernel, bias);

    // Viterbi: one block per batch
    crf_viterbi_kernel<<<BB, 512, VIT_SMEM_BYTES>>>(trans, lb, rb, out);
}

// round 16
// speedup vs baseline: 1.0031x; 1.0031x over previous
#include <cuda_runtime.h>
#include <cstdint>

// Problem dimensions (fixed by the reference)
#define BB 64
#define TT 512
#define DD 1024
#define UU 128

// Scratch for logits [B, T, U] fp32 = 16 MB (device global: no allocs allowed)
__device__ float g_logits[BB * TT * UU];

// ---------------------------------------------------------------------------
// Packed f32x2 helpers (full-rate FMA pipe on sm_103a; FFMA 3-reg is half-rate)
// ---------------------------------------------------------------------------
__device__ __forceinline__ unsigned long long pack2same(float a) {
    unsigned long long r;
    asm("mov.b64 %0, {%1, %1};" : "=l"(r) : "r"(__float_as_uint(a)));
    return r;
}
__device__ __forceinline__ void fma2(unsigned long long& d,
                                     unsigned long long a,
                                     unsigned long long b) {
    asm("fma.rn.f32x2 %0, %1, %2, %0;" : "+l"(d) : "l"(a), "l"(b));
}
__device__ __forceinline__ void unpack2(unsigned long long v, float& lo, float& hi) {
    unsigned int a, b;
    asm("mov.b64 {%0, %1}, %2;" : "=r"(a), "=r"(b) : "l"(v));
    lo = __uint_as_float(a);
    hi = __uint_as_float(b);
}

// ---------------------------------------------------------------------------
// GEMM: logits[m, u] = sum_d X[m, d] * W[d, u] + bias[u]
// M = B*T = 32768, N = 128, K = 1024. Tile 128x128, TK=16, 256 threads,
// each thread an 8x8 micro-tile held as 8x4 f32x2 accumulators.
// ---------------------------------------------------------------------------
#define TMr 128
#define TNr 128
#define TKr 16

__global__ __launch_bounds__(256)
void crf_gemm_kernel(const float* __restrict__ X,
                     const float* __restrict__ W,
                     const float* __restrict__ bias) {
    __shared__ float As[TKr * TMr];  // transposed: As[k][m]
    __shared__ float Bs[TKr * TNr];  // Bs[k][n]

    const int tid = threadIdx.x;
    const int tx = tid & 15;   // 16 col-groups of 8
    const int ty = tid >> 4;   // 16 row-groups of 8
    const long row0 = (long)blockIdx.x * TMr;

    unsigned long long acc[8][4];
#pragma unroll
    for (int r = 0; r < 8; ++r)
#pragma unroll
        for (int p = 0; p < 4; ++p) acc[r][p] = 0ULL;

    for (int kb = 0; kb < DD; kb += TKr) {
        // Load A tile (128 rows x 16 k) transposed into As[k][m]
#pragma unroll
        for (int q = 0; q < 2; ++q) {
            int idx4 = tid * 2 + q;          // 0..511 float4s
            int m = idx4 >> 2;               // 4 float4 per row (TK=16)
            int kq = (idx4 & 3) * 4;
            float4 f = *(const float4*)&X[(row0 + m) * DD + kb + kq];
            As[(kq + 0) * TMr + m] = f.x;
            As[(kq + 1) * TMr + m] = f.y;
            As[(kq + 2) * TMr + m] = f.z;
            As[(kq + 3) * TMr + m] = f.w;
        }
        // Load B tile (16 k x 128 n)
#pragma unroll
        for (int q = 0; q < 2; ++q) {
            int idx4 = tid * 2 + q;          // 0..511 float4s
            int k = idx4 >> 5;               // 32 float4 per row (TN=128)
            int n4 = (idx4 & 31) * 4;
            *(float4*)&Bs[k * TNr + n4] =
                *(const float4*)&W[(long)(kb + k) * UU + n4];
        }
        __syncthreads();

#pragma unroll
        for (int k = 0; k < TKr; ++k) {
            float4 a0 = *(const float4*)&As[k * TMr + ty * 8];
            float4 a1 = *(const float4*)&As[k * TMr + ty * 8 + 4];
            float av[8] = {a0.x, a0.y, a0.z, a0.w, a1.x, a1.y, a1.z, a1.w};
            ulonglong2 b01 = *(const ulonglong2*)&Bs[k * TNr + tx * 8];
            ulonglong2 b23 = *(const ulonglong2*)&Bs[k * TNr + tx * 8 + 4];
            unsigned long long bb[4] = {b01.x, b01.y, b23.x, b23.y};
#pragma unroll
            for (int r = 0; r < 8; ++r) {
                unsigned long long ap = pack2same(av[r]);
#pragma unroll
                for (int p = 0; p < 4; ++p) fma2(acc[r][p], ap, bb[p]);
            }
        }
        __syncthreads();
    }

    // Epilogue: + bias, store to g_logits
    float4 bv0 = *(const float4*)&bias[tx * 8];
    float4 bv1 = *(const float4*)&bias[tx * 8 + 4];
    float bcol[8] = {bv0.x, bv0.y, bv0.z, bv0.w, bv1.x, bv1.y, bv1.z, bv1.w};

#pragma unroll
    for (int r = 0; r < 8; ++r) {
        float o[8];
#pragma unroll
        for (int p = 0; p < 4; ++p) unpack2(acc[r][p], o[2 * p], o[2 * p + 1]);
#pragma unroll
        for (int c = 0; c < 8; ++c) o[c] += bcol[c];
        long row = row0 + ty * 8 + r;
        *(float4*)&g_logits[row * UU + tx * 8] =
            make_float4(o[0], o[1], o[2], o[3]);
        *(float4*)&g_logits[row * UU + tx * 8 + 4] =
            make_float4(o[4], o[5], o[6], o[7]);
    }
}

// ---------------------------------------------------------------------------
// Viterbi: one CTA per batch, 512 threads = 4 i-slices x 128 j.
// trans transposed in SMEM, stride 132 (conflict-free LDS.128).
// Backpointers kept in SMEM (511 x 128 uint8) so backtrace is LDS-latency.
// Tie-breaking matches jnp.argmax (first max) via strict-> updates and
// ascending slice merge order.
// ---------------------------------------------------------------------------
#define SM_TRANS_STRIDE 132
// smem layout sizes (bytes):
//   transT : 128*132*4 = 67584
//   v      : 128*4     = 512
//   redv   : 512*4     = 2048
//   redi   : 512*4     = 2048
//   bp     : 511*128   = 65408
#define VIT_SMEM_BYTES (67584 + 512 + 2048 + 2048 + 65408)

__global__ __launch_bounds__(512, 1)
void crf_viterbi_kernel(const float* __restrict__ trans,
                        const float* __restrict__ lb,
                        const float* __restrict__ rb,
                        float* __restrict__ out) {
    extern __shared__ char smem[];
    float* transT = (float*)smem;                       // [128][132]
    float* v = transT + UU * SM_TRANS_STRIDE;           // [128]
    float* redv = v + UU;                               // [512]
    int* redi = (int*)(redv + 512);                     // [512]
    unsigned char* bp = (unsigned char*)(redi + 512);   // [511][128]

    const int tid = threadIdx.x;
    const int b = blockIdx.x;
    const float* lg_base = g_logits + (size_t)b * TT * UU;

    // Load transposed transition matrix: transT[j][i] = trans[i][j]
    for (int idx = tid; idx < UU * UU; idx += 512) {
        int i = idx >> 7;
        int jj = idx & 127;
        transT[jj * SM_TRANS_STRIDE + i] = trans[idx];
    }
    // Init v with t=0 logits + left boundary
    if (tid < UU) v[tid] = lg_base[tid] + lb[tid];
    __syncthreads();

    const int j = tid & 127;
    const int s = tid >> 7;          // i-slice 0..3
    const int ibase = s * 32;
    const float4* trow = (const float4*)(transT + j * SM_TRANS_STRIDE + ibase);
    const float4* vrow = (const float4*)(v + ibase);

    for (int t = 1; t < TT; ++t) {
        // Prefetch this step's logit (consumed after the barrier)
        float lg = 0.0f;
        if (tid < UU) {
            lg = lg_base[t * UU + tid];
            if (t == TT - 1) lg += rb[tid];
        }

        // Partial max/argmax over this thread's 32 i's
        float m = -3.4e38f;
        int bi = ibase;
#pragma unroll
        for (int k = 0; k < 8; ++k) {
            float4 tr = trow[k];
            float4 vv = vrow[k];   // broadcast (same addr across warp)
            float s0 = vv.x + tr.x;
            float s1 = vv.y + tr.y;
            float s2 = vv.z + tr.z;
            float s3 = vv.w + tr.w;
            if (s0 > m) { m = s0; bi = ibase + 4 * k + 0; }
            if (s1 > m) { m = s1; bi = ibase + 4 * k + 1; }
            if (s2 > m) { m = s2; bi = ibase + 4 * k + 2; }
            if (s3 > m) { m = s3; bi = ibase + 4 * k + 3; }
        }
        redv[tid] = m;
        redi[tid] = bi;
        __syncthreads();

        if (tid < UU) {
            float best = redv[tid];
            int bidx = redi[tid];
#pragma unroll
            for (int ss = 1; ss < 4; ++ss) {
                float c = redv[ss * 128 + tid];
                int ci = redi[ss * 128 + tid];
                if (c > best) { best = c; bidx = ci; }  // strict: lowest i wins ties
            }
            v[tid] = best + lg;
            bp[(t - 1) * UU + tid] = (unsigned char)bidx;
        }
        __syncthreads();
    }

    // Final argmax (first max) + backtrace — SMEM pointer chase, ~29 cyc/step
    if (tid == 0) {
        float best = v[0];
        int tag = 0;
        for (int jj = 1; jj < UU; ++jj) {
            if (v[jj] > best) { best = v[jj]; tag = jj; }
        }
        out[(size_t)b * TT + (TT - 1)] = (float)tag;
        for (int t = TT - 2; t >= 0; --t) {
            tag = bp[t * UU + tag];
            out[(size_t)b * TT + t] = (float)tag;
        }
    }
}

// ---------------------------------------------------------------------------
extern "C" void kernel_launch(void* const* d_in, const int* in_sizes, int n_in,
                              void* d_out, int out_size) {
    const float* x = (const float*)d_in[0];       // [64, 512, 1024]
    const float* kernel = (const float*)d_in[1];  // [1024, 128]
    const float* bias = (const float*)d_in[2];    // [128]
    const float* trans = (const float*)d_in[3];   // [128, 128]
    const float* lb = (const float*)d_in[4];      // [128]
    const float* rb = (const float*)d_in[5];      // [128]
    float* out = (float*)d_out;                   // [64, 512] float32

    static bool attr_set = false;
    if (!attr_set) {
        cudaFuncSetAttribute(crf_viterbi_kernel,
                             cudaFuncAttributeMaxDynamicSharedMemorySize,
                             VIT_SMEM_BYTES);
        attr_set = true;
    }

    // GEMM: 32768 rows / 128 per block = 256 blocks
    crf_gemm_kernel<<<(BB * TT) / TMr, 256>>>(x, kernel, bias);

    // Viterbi: one block per batch
    crf_viterbi_kernel<<<BB, 512, VIT_SMEM_BYTES>>>(trans, lb, rb, out);
}